// round 9
// baseline (speedup 1.0000x reference)
#include <cuda_runtime.h>
#include <cuda_fp16.h>

// ---------------------------------------------------------------------------
// BlocCircLinear via mma.sync m16n8k16 (f16 in / f32 acc), compute_103-safe.
//   D[b=32, 8192] = X[32, 8192] @ W^T,  W block-circulant from blocks[512][16][16].
// R9: SINGLE KERNEL. Evidence: each launch costs ~4us fixed overhead on this
//   harness (convert 4.5us / reduce 5.8us for near-zero busy%), while the
//   mainloop already runs at the HMMA pipe floor (~10.6us).
//   - fused f32->f16 staging (L2-hot in-graph)
//   - f16x2 partials (4 MB)
//   - cross-CTA K-split reduction fused via threadfence + monotonic atomic
//     counters: the 8th-arriving CTA of each T group sums the 8 partials and
//     writes d_out. Deterministic (fixed ks summation order).
// ---------------------------------------------------------------------------

#define BATCH   32
#define NBLK    512
#define DIM     8192
#define NTILES  16        // 8192 / 512 output cols
#define KSPLIT  8         // K split across CTAs -> 1024 per CTA
#define JSTEPS2 32        // 512 k per half / 16
#define THREADS 512
#define PSZ     (BATCH * DIM)

#define XS_STR   1032                       // halves per x row (1024 + 8 pad)
#define BLK_N    95                         // blocks staged per CTA
#define PAD_LO   512                        // underflow pad (B prefetch d = -1)
#define PAD_HI   1024                       // overflow pad (A prefetch @ last j)
#define OFF_BLK  PAD_LO
#define OFF_XS   (PAD_LO + BLK_N * 512)     // 512 + 48640
#define SMEM_TOT (OFF_XS + BATCH * XS_STR * 2 + PAD_HI)   // 116224

__device__ __half   g_parth[KSPLIT * PSZ];  // f16 partials [8][32][8192], 4 MB
__device__ unsigned g_cnt[NTILES];          // monotonic arrival counters

static __device__ __forceinline__ unsigned swzb(unsigned off) {
    return off ^ ((off >> 3) & 0x70);
}
static __device__ __forceinline__ unsigned smem_u32(const void* p) {
    return (unsigned)__cvta_generic_to_shared(p);
}
static __device__ __forceinline__ void ldsm4(unsigned* r, unsigned addr) {
    asm volatile("ldmatrix.sync.aligned.m8n8.x4.shared.b16 {%0,%1,%2,%3}, [%4];"
                 : "=r"(r[0]), "=r"(r[1]), "=r"(r[2]), "=r"(r[3]) : "r"(addr));
}
static __device__ __forceinline__ void mma16816(float* c, const unsigned* a,
                                                unsigned b0, unsigned b1) {
    asm volatile(
        "mma.sync.aligned.m16n8k16.row.col.f32.f16.f16.f32 "
        "{%0,%1,%2,%3}, {%4,%5,%6,%7}, {%8,%9}, {%0,%1,%2,%3};"
        : "+f"(c[0]), "+f"(c[1]), "+f"(c[2]), "+f"(c[3])
        : "r"(a[0]), "r"(a[1]), "r"(a[2]), "r"(a[3]), "r"(b0), "r"(b1));
}
static __device__ __forceinline__ uint4 cvt8(float4 a, float4 b) {
    __half2 h0 = __float22half2_rn(make_float2(a.x, a.y));
    __half2 h1 = __float22half2_rn(make_float2(a.z, a.w));
    __half2 h2 = __float22half2_rn(make_float2(b.x, b.y));
    __half2 h3 = __float22half2_rn(make_float2(b.z, b.w));
    uint4 o;
    o.x = *reinterpret_cast<unsigned*>(&h0);
    o.y = *reinterpret_cast<unsigned*>(&h1);
    o.z = *reinterpret_cast<unsigned*>(&h2);
    o.w = *reinterpret_cast<unsigned*>(&h3);
    return o;
}

// ---------------------------------------------------------------------------
// Single kernel: staging + GEMM + partial store + fused cross-CTA reduction.
// grid = NTILES * KSPLIT = 128 CTAs x 512 threads.
// ---------------------------------------------------------------------------
extern __shared__ __align__(1024) char smem[];

__global__ void __launch_bounds__(THREADS, 1) bc_mma_kernel(
    const float* __restrict__ x32, const float* __restrict__ blk32,
    float* __restrict__ out)
{
    const int tid  = threadIdx.x;
    const int wid  = tid >> 5;
    const int lane = tid & 31;
    const int grp  = wid & 7;                 // col-group 0..7
    const int kh   = wid >> 3;                // k-half 0/1
    const int T    = blockIdx.x & (NTILES - 1);
    const int ks   = blockIdx.x >> 4;
    const int smin = (T * 32 - ks * 64 - 63) & (NBLK - 1);

    char* blk = smem + OFF_BLK;
    char* xsb = smem + OFF_XS;

    // ---- stage + convert: x chunk (32 x 1024 f32) and 95 blocks ----
    {
        const float4* xf = reinterpret_cast<const float4*>(x32);
#pragma unroll
        for (int i = tid; i < 4096; i += THREADS) {   // 16B-half chunks
            int row = i >> 7, cc = i & 127;
            const float4* p = xf + row * 2048 + ks * 256 + cc * 2;
            float4 a = p[0], b = p[1];
            *reinterpret_cast<uint4*>(xsb + row * (XS_STR * 2) + cc * 16) =
                cvt8(a, b);
        }
        const float4* bf = reinterpret_cast<const float4*>(blk32);
#pragma unroll
        for (int i = tid; i < BLK_N * 32; i += THREADS) {
            int d = i >> 5, w = i & 31;
            int s = (smin + d) & (NBLK - 1);
            const float4* p = bf + s * 64 + w * 2;
            float4 a = p[0], b = p[1];
            *reinterpret_cast<uint4*>(blk + d * 512 + swzb(w * 16)) =
                cvt8(a, b);
        }
        __syncthreads();
    }

    // ---- lane-invariant ldmatrix addresses ----
    const int a0 = grp * 4;                   // warp's first block-col
    unsigned arow = (unsigned)(lane & 15);
    unsigned kadd = (unsigned)((lane >> 4) * 8);
    unsigned aA0 = smem_u32(xsb) + arow * (XS_STR * 2) + (unsigned)(kh * 1024)
                 + kadd * 2;
    unsigned aA1 = aA0 + 16 * (XS_STR * 2);
    unsigned pr   = (unsigned)(((lane >> 4) & 1) * 8 + (lane & 7));
    unsigned koff = (unsigned)(((lane >> 3) & 1) * 16);
    unsigned bl   = swzb(pr * 32 + koff);
    unsigned bbase = smem_u32(blk) + bl;
    const int d0 = a0 + 63 - kh * 32;         // block window start for this half

    float acc[2][8][4] = {};

    // ---- preload j=0 fragments ----
    unsigned A0[4], A1[4], Bf[4][4];
    ldsm4(A0, aA0);
    ldsm4(A1, aA1);
#pragma unroll
    for (int r = 0; r < 4; ++r)
        ldsm4(Bf[r], bbase + (unsigned)((d0 + r) * 512));
    unsigned bPre = bbase + (unsigned)((d0 - 1) * 512);   // next-step new frag

#pragma unroll 4
    for (int j = 0; j < JSTEPS2; ++j) {
        // prefetch next step (overreads land in smem pads; values unused)
        unsigned An0[4], An1[4], Bn[4];
        ldsm4(An0, aA0 + 32);
        ldsm4(An1, aA1 + 32);
        ldsm4(Bn, bPre);

        // 16 MMAs on current fragments
#pragma unroll
        for (int r = 0; r < 4; ++r) {
            mma16816(acc[0][2 * r],     A0, Bf[r][0], Bf[r][1]);
            mma16816(acc[1][2 * r],     A1, Bf[r][0], Bf[r][1]);
            mma16816(acc[0][2 * r + 1], A0, Bf[r][2], Bf[r][3]);
            mma16816(acc[1][2 * r + 1], A1, Bf[r][2], Bf[r][3]);
        }

        // rotate: window shifts by one block per k-step (circulant)
#pragma unroll
        for (int t = 0; t < 4; ++t) {
            Bf[3][t] = Bf[2][t];
            Bf[2][t] = Bf[1][t];
            Bf[1][t] = Bf[0][t];
            Bf[0][t] = Bn[t];
            A0[t] = An0[t];
            A1[t] = An1[t];
        }
        aA0 += 32; aA1 += 32;
        bPre -= 512;
    }

    // ---- combine k-halves in smem (conflict-free 16B-interleaved layout) ----
    __syncthreads();                          // everyone done reading staged smem
    if (kh == 1) {
#pragma unroll
        for (int m = 0; m < 2; ++m)
#pragma unroll
            for (int nf = 0; nf < 8; ++nf) {
                int rr = m * 8 + nf;
                *reinterpret_cast<float4*>(
                    smem + (rr * 8 + grp) * 512 + lane * 16) =
                    make_float4(acc[m][nf][0], acc[m][nf][1],
                                acc[m][nf][2], acc[m][nf][3]);
            }
    }
    __syncthreads();

    // ---- epilogue: warps 0-7 add other half, store f16x2 partials ----
    if (kh == 0) {
        const int q  = lane & 3;
        const int rw = lane >> 2;
        __half* part = g_parth + ks * PSZ;
#pragma unroll
        for (int m = 0; m < 2; ++m) {
#pragma unroll
            for (int nf = 0; nf < 8; ++nf) {
                int rr = m * 8 + nf;
                float4 o = *reinterpret_cast<float4*>(
                    smem + (rr * 8 + grp) * 512 + lane * 16);
                int col = T * 512 + (a0 + (nf >> 1)) * 16 + (nf & 1) * 8 + q * 2;
                int b0  = m * 16 + rw;
                *reinterpret_cast<__half2*>(part + b0 * DIM + col) =
                    __floats2half2_rn(acc[m][nf][0] + o.x, acc[m][nf][1] + o.y);
                *reinterpret_cast<__half2*>(part + (b0 + 8) * DIM + col) =
                    __floats2half2_rn(acc[m][nf][2] + o.z, acc[m][nf][3] + o.w);
            }
        }
    }

    // ---- fused cross-CTA reduction: last arriver of each T group sums ----
    __shared__ unsigned s_last;
    __syncthreads();                          // all partial stores issued
    if (tid == 0) {
        __threadfence();                      // release partials
        unsigned old = atomicAdd(&g_cnt[T], 1u);
        s_last = ((old & (KSPLIT - 1u)) == KSPLIT - 1u) ? 1u : 0u;
    }
    __syncthreads();
    if (s_last) {
        __threadfence();                      // acquire peers' partials
        // 512 threads reduce this T group's 32 x 512 output chunk.
        // thread: 8 consecutive cols (uint4 of halves), 4 b-passes.
#pragma unroll
        for (int pass = 0; pass < 4; ++pass) {
            const int b  = (tid >> 6) + pass * 8;
            const int cb = (tid & 63) * 8;
            const int off = b * DIM + T * 512 + cb;
            float v[8] = {};
#pragma unroll
            for (int ksp = 0; ksp < KSPLIT; ++ksp) {
                uint4 u = *reinterpret_cast<const uint4*>(
                    g_parth + ksp * PSZ + off);
                float2 f0 = __half22float2(*reinterpret_cast<__half2*>(&u.x));
                float2 f1 = __half22float2(*reinterpret_cast<__half2*>(&u.y));
                float2 f2 = __half22float2(*reinterpret_cast<__half2*>(&u.z));
                float2 f3 = __half22float2(*reinterpret_cast<__half2*>(&u.w));
                v[0] += f0.x; v[1] += f0.y; v[2] += f1.x; v[3] += f1.y;
                v[4] += f2.x; v[5] += f2.y; v[6] += f3.x; v[7] += f3.y;
            }
            *reinterpret_cast<float4*>(out + off) =
                make_float4(v[0], v[1], v[2], v[3]);
            *reinterpret_cast<float4*>(out + off + 4) =
                make_float4(v[4], v[5], v[6], v[7]);
        }
    }
}

// ---------------------------------------------------------------------------
extern "C" void kernel_launch(void* const* d_in, const int* in_sizes, int n_in,
                              void* d_out, int out_size)
{
    const float* x   = (const float*)d_in[0];
    const float* blk = (const float*)d_in[1];
    float* out = (float*)d_out;

    cudaFuncSetAttribute(bc_mma_kernel,
                         cudaFuncAttributeMaxDynamicSharedMemorySize, SMEM_TOT);

    bc_mma_kernel<<<NTILES * KSPLIT, THREADS, SMEM_TOT>>>(x, blk, out);
}

// round 10
// speedup vs baseline: 1.1039x; 1.1039x over previous
#include <cuda_runtime.h>
#include <cuda_fp16.h>

// ---------------------------------------------------------------------------
// BlocCircLinear via mma.sync m16n8k16 (f16 in / f32 acc), compute_103-safe.
//   D[b=32, 8192] = X[32, 8192] @ W^T,  W block-circulant from blocks[512][16][16].
// R10: R8 two-kernel structure (proven 21.2us) + R9's f16 partials (proven
//   rel_err 3.56e-4): partial traffic 16MB -> 8MB, lean high-MLP reduce.
//   - bc_mma: 128 CTAs x 512 thr, fused f32->f16 staging, HMMA mainloop
//     at the tensor-pipe floor, f16x2 partial store.
//   - reduce: 32768 threads, 8 independent LDG.128 each (MLP 8), f32 out.
// ---------------------------------------------------------------------------

#define BATCH   32
#define NBLK    512
#define DIM     8192
#define NTILES  16        // 8192 / 512 output cols
#define KSPLIT  8         // K split across CTAs -> 1024 per CTA
#define JSTEPS2 32        // 512 k per half / 16
#define THREADS 512
#define PSZ     (BATCH * DIM)

#define XS_STR   1032                       // halves per x row (1024 + 8 pad)
#define BLK_N    95                         // blocks staged per CTA
#define PAD_LO   512                        // underflow pad (B prefetch d = -1)
#define PAD_HI   1024                       // overflow pad (A prefetch @ last j)
#define OFF_BLK  PAD_LO
#define OFF_XS   (PAD_LO + BLK_N * 512)     // 512 + 48640
#define SMEM_TOT (OFF_XS + BATCH * XS_STR * 2 + PAD_HI)   // 116224

__device__ __half g_parth[KSPLIT * PSZ];    // f16 partials [8][32][8192], 4 MB

static __device__ __forceinline__ unsigned swzb(unsigned off) {
    return off ^ ((off >> 3) & 0x70);
}
static __device__ __forceinline__ unsigned smem_u32(const void* p) {
    return (unsigned)__cvta_generic_to_shared(p);
}
static __device__ __forceinline__ void ldsm4(unsigned* r, unsigned addr) {
    asm volatile("ldmatrix.sync.aligned.m8n8.x4.shared.b16 {%0,%1,%2,%3}, [%4];"
                 : "=r"(r[0]), "=r"(r[1]), "=r"(r[2]), "=r"(r[3]) : "r"(addr));
}
static __device__ __forceinline__ void mma16816(float* c, const unsigned* a,
                                                unsigned b0, unsigned b1) {
    asm volatile(
        "mma.sync.aligned.m16n8k16.row.col.f32.f16.f16.f32 "
        "{%0,%1,%2,%3}, {%4,%5,%6,%7}, {%8,%9}, {%0,%1,%2,%3};"
        : "+f"(c[0]), "+f"(c[1]), "+f"(c[2]), "+f"(c[3])
        : "r"(a[0]), "r"(a[1]), "r"(a[2]), "r"(a[3]), "r"(b0), "r"(b1));
}
static __device__ __forceinline__ uint4 cvt8(float4 a, float4 b) {
    __half2 h0 = __float22half2_rn(make_float2(a.x, a.y));
    __half2 h1 = __float22half2_rn(make_float2(a.z, a.w));
    __half2 h2 = __float22half2_rn(make_float2(b.x, b.y));
    __half2 h3 = __float22half2_rn(make_float2(b.z, b.w));
    uint4 o;
    o.x = *reinterpret_cast<unsigned*>(&h0);
    o.y = *reinterpret_cast<unsigned*>(&h1);
    o.z = *reinterpret_cast<unsigned*>(&h2);
    o.w = *reinterpret_cast<unsigned*>(&h3);
    return o;
}

// ---------------------------------------------------------------------------
// Kernel 1: block-circulant GEMM with fused f32->f16 staging.
// grid = NTILES * KSPLIT = 128 CTAs x 512 threads.
// ---------------------------------------------------------------------------
extern __shared__ __align__(1024) char smem[];

__global__ void __launch_bounds__(THREADS, 1) bc_mma_kernel(
    const float* __restrict__ x32, const float* __restrict__ blk32)
{
    const int tid  = threadIdx.x;
    const int wid  = tid >> 5;
    const int lane = tid & 31;
    const int grp  = wid & 7;                 // col-group 0..7
    const int kh   = wid >> 3;                // k-half 0/1
    const int T    = blockIdx.x & (NTILES - 1);
    const int ks   = blockIdx.x >> 4;
    const int smin = (T * 32 - ks * 64 - 63) & (NBLK - 1);

    char* blk = smem + OFF_BLK;
    char* xsb = smem + OFF_XS;

    // ---- stage + convert: x chunk (32 x 1024 f32) and 95 blocks ----
    {
        const float4* xf = reinterpret_cast<const float4*>(x32);
#pragma unroll
        for (int i = tid; i < 4096; i += THREADS) {   // 16B-half chunks
            int row = i >> 7, cc = i & 127;
            const float4* p = xf + row * 2048 + ks * 256 + cc * 2;
            float4 a = p[0], b = p[1];
            *reinterpret_cast<uint4*>(xsb + row * (XS_STR * 2) + cc * 16) =
                cvt8(a, b);
        }
        const float4* bf = reinterpret_cast<const float4*>(blk32);
#pragma unroll
        for (int i = tid; i < BLK_N * 32; i += THREADS) {
            int d = i >> 5, w = i & 31;
            int s = (smin + d) & (NBLK - 1);
            const float4* p = bf + s * 64 + w * 2;
            float4 a = p[0], b = p[1];
            *reinterpret_cast<uint4*>(blk + d * 512 + swzb(w * 16)) =
                cvt8(a, b);
        }
        __syncthreads();
    }

    // ---- lane-invariant ldmatrix addresses ----
    const int a0 = grp * 4;                   // warp's first block-col
    unsigned arow = (unsigned)(lane & 15);
    unsigned kadd = (unsigned)((lane >> 4) * 8);
    unsigned aA0 = smem_u32(xsb) + arow * (XS_STR * 2) + (unsigned)(kh * 1024)
                 + kadd * 2;
    unsigned aA1 = aA0 + 16 * (XS_STR * 2);
    unsigned pr   = (unsigned)(((lane >> 4) & 1) * 8 + (lane & 7));
    unsigned koff = (unsigned)(((lane >> 3) & 1) * 16);
    unsigned bl   = swzb(pr * 32 + koff);
    unsigned bbase = smem_u32(blk) + bl;
    const int d0 = a0 + 63 - kh * 32;         // block window start for this half

    float acc[2][8][4] = {};

    // ---- preload j=0 fragments ----
    unsigned A0[4], A1[4], Bf[4][4];
    ldsm4(A0, aA0);
    ldsm4(A1, aA1);
#pragma unroll
    for (int r = 0; r < 4; ++r)
        ldsm4(Bf[r], bbase + (unsigned)((d0 + r) * 512));
    unsigned bPre = bbase + (unsigned)((d0 - 1) * 512);   // next-step new frag

#pragma unroll 4
    for (int j = 0; j < JSTEPS2; ++j) {
        // prefetch next step (overreads land in smem pads; values unused)
        unsigned An0[4], An1[4], Bn[4];
        ldsm4(An0, aA0 + 32);
        ldsm4(An1, aA1 + 32);
        ldsm4(Bn, bPre);

        // 16 MMAs on current fragments
#pragma unroll
        for (int r = 0; r < 4; ++r) {
            mma16816(acc[0][2 * r],     A0, Bf[r][0], Bf[r][1]);
            mma16816(acc[1][2 * r],     A1, Bf[r][0], Bf[r][1]);
            mma16816(acc[0][2 * r + 1], A0, Bf[r][2], Bf[r][3]);
            mma16816(acc[1][2 * r + 1], A1, Bf[r][2], Bf[r][3]);
        }

        // rotate: window shifts by one block per k-step (circulant)
#pragma unroll
        for (int t = 0; t < 4; ++t) {
            Bf[3][t] = Bf[2][t];
            Bf[2][t] = Bf[1][t];
            Bf[1][t] = Bf[0][t];
            Bf[0][t] = Bn[t];
            A0[t] = An0[t];
            A1[t] = An1[t];
        }
        aA0 += 32; aA1 += 32;
        bPre -= 512;
    }

    // ---- combine k-halves in smem (conflict-free 16B-interleaved layout) ----
    __syncthreads();                          // everyone done reading staged smem
    if (kh == 1) {
#pragma unroll
        for (int m = 0; m < 2; ++m)
#pragma unroll
            for (int nf = 0; nf < 8; ++nf) {
                int rr = m * 8 + nf;
                *reinterpret_cast<float4*>(
                    smem + (rr * 8 + grp) * 512 + lane * 16) =
                    make_float4(acc[m][nf][0], acc[m][nf][1],
                                acc[m][nf][2], acc[m][nf][3]);
            }
    }
    __syncthreads();

    // ---- epilogue: warps 0-7 add other half, store f16x2 partials ----
    if (kh == 0) {
        const int q  = lane & 3;
        const int rw = lane >> 2;
        __half* part = g_parth + ks * PSZ;
#pragma unroll
        for (int m = 0; m < 2; ++m) {
#pragma unroll
            for (int nf = 0; nf < 8; ++nf) {
                int rr = m * 8 + nf;
                float4 o = *reinterpret_cast<float4*>(
                    smem + (rr * 8 + grp) * 512 + lane * 16);
                int col = T * 512 + (a0 + (nf >> 1)) * 16 + (nf & 1) * 8 + q * 2;
                int b0  = m * 16 + rw;
                *reinterpret_cast<__half2*>(part + b0 * DIM + col) =
                    __floats2half2_rn(acc[m][nf][0] + o.x, acc[m][nf][1] + o.y);
                *reinterpret_cast<__half2*>(part + (b0 + 8) * DIM + col) =
                    __floats2half2_rn(acc[m][nf][2] + o.z, acc[m][nf][3] + o.w);
            }
        }
    }
}

// ---------------------------------------------------------------------------
// Kernel 2: reduce the 8 f16 partials. 32768 threads, 8 output cols each,
// 8 independent LDG.128 per thread (MLP 8), f32 result.
// ---------------------------------------------------------------------------
__global__ void __launch_bounds__(256) reduce_kernel(float* __restrict__ out)
{
    int i  = blockIdx.x * 256 + threadIdx.x;  // 0..32767
    int b  = i >> 10;                         // batch row 0..31
    int cg = i & 1023;                        // col-group of 8
    int off = b * DIM + cg * 8;

    float v[8] = {};
#pragma unroll
    for (int ksp = 0; ksp < KSPLIT; ++ksp) {
        uint4 u = *reinterpret_cast<const uint4*>(g_parth + ksp * PSZ + off);
        float2 f0 = __half22float2(*reinterpret_cast<__half2*>(&u.x));
        float2 f1 = __half22float2(*reinterpret_cast<__half2*>(&u.y));
        float2 f2 = __half22float2(*reinterpret_cast<__half2*>(&u.z));
        float2 f3 = __half22float2(*reinterpret_cast<__half2*>(&u.w));
        v[0] += f0.x; v[1] += f0.y; v[2] += f1.x; v[3] += f1.y;
        v[4] += f2.x; v[5] += f2.y; v[6] += f3.x; v[7] += f3.y;
    }
    *reinterpret_cast<float4*>(out + off)     = make_float4(v[0], v[1], v[2], v[3]);
    *reinterpret_cast<float4*>(out + off + 4) = make_float4(v[4], v[5], v[6], v[7]);
}

// ---------------------------------------------------------------------------
extern "C" void kernel_launch(void* const* d_in, const int* in_sizes, int n_in,
                              void* d_out, int out_size)
{
    const float* x   = (const float*)d_in[0];
    const float* blk = (const float*)d_in[1];
    float* out = (float*)d_out;

    cudaFuncSetAttribute(bc_mma_kernel,
                         cudaFuncAttributeMaxDynamicSharedMemorySize, SMEM_TOT);

    bc_mma_kernel<<<NTILES * KSPLIT, THREADS, SMEM_TOT>>>(x, blk);
    reduce_kernel<<<128, 256>>>(out);
}